// round 3
// baseline (speedup 1.0000x reference)
#include <cuda_runtime.h>
#include <cuda_bf16.h>

#define CCH   256
#define HH    360
#define WW    360
#define NPTS  1024
#define CPB   16
#define NPAIR (CPB / 2)   // center pairs per block

typedef unsigned long long ull;

// Scratch: a1[m][k] = f1 @ w3 ; a2p[n][k] = b3[k] - (f2 @ w3)[n][k]
__device__ float g_a1[NPTS * 32];
__device__ float g_a2p[NPTS * 32];

#define FFMA2(acc, x, w) \
    asm("fma.rn.f32x2 %0, %1, %2, %0;" : "+l"(acc) : "l"(x), "l"(w))
#define FADD2(d, a, b) \
    asm("add.rn.f32x2 %0, %1, %2;" : "=l"(d) : "l"(a), "l"(b))

__device__ __forceinline__ ull pack2(float a, float b) {
    ull r;
    asm("mov.b64 %0, {%1, %2};" : "=l"(r) : "f"(a), "f"(b));
    return r;
}
__device__ __forceinline__ float2 unpack2(ull v) {
    float2 f;
    asm("mov.b64 {%0, %1}, %2;" : "=f"(f.x), "=f"(f.y) : "l"(v));
    return f;
}

// ---------------------------------------------------------------------------
// Kernel 1: gather + 256->256->128 MLP (relu) + @w3 projection to 32 dims.
// 16 centers per block (8 f32x2 pairs), 256 threads, 128 blocks.
// All packed-f32x2 math (FFMA2): 2 centers per instruction.
// ---------------------------------------------------------------------------
__global__ __launch_bounds__(256) void project_kernel(
    const float* __restrict__ feature,
    const int*   __restrict__ idx1,
    const int*   __restrict__ idx2,
    const float* __restrict__ w1, const float* __restrict__ b1,
    const float* __restrict__ w2, const float* __restrict__ b2,
    const float* __restrict__ w3, const float* __restrict__ b3)
{
    __shared__ float2 xs2[NPAIR][256];   // 16KB gathered features, [pair][chan]
    __shared__ float2 h1p[NPAIR][256];   // 16KB layer1 out, [pair][col]
    __shared__ float2 h2p[NPAIR][128];   // 8KB  layer2 out, [pair][col]

    const int tid = threadIdx.x;
    const int g0  = blockIdx.x * CPB;
    const bool frame2 = (g0 >= NPTS);
    const int* __restrict__ idx = frame2 ? idx2 : idx1;
    const int  i0 = frame2 ? (g0 - NPTS) : g0;

    // gather: thread tid loads channel tid for each of the 16 centers
    #pragma unroll
    for (int t = 0; t < CPB; t++) {
        int b  = __ldg(&idx[i0 + t]);
        int hh = __ldg(&idx[NPTS + i0 + t]);
        int ww = __ldg(&idx[2 * NPTS + i0 + t]);
        long off = (((long)b * CCH + tid) * HH + hh) * (long)WW + ww;
        ((float*)&xs2[t >> 1][tid])[t & 1] = __ldg(&feature[off]);
    }
    __syncthreads();

    // layer 1: h1 = relu(x @ w1 + b1); thread tid owns output column tid.
    {
        ull acc[NPAIR];
        {
            float bias = b1[tid];
            ull bp = pack2(bias, bias);
            #pragma unroll
            for (int p = 0; p < NPAIR; p++) acc[p] = bp;
        }
        #pragma unroll 2
        for (int c = 0; c < 256; c += 4) {
            float v0 = w1[(c + 0) * 256 + tid];
            float v1 = w1[(c + 1) * 256 + tid];
            float v2 = w1[(c + 2) * 256 + tid];
            float v3 = w1[(c + 3) * 256 + tid];
            ull p0 = pack2(v0, v0), p1 = pack2(v1, v1);
            ull p2 = pack2(v2, v2), p3 = pack2(v3, v3);
            #pragma unroll
            for (int p = 0; p < NPAIR; p++) {
                ulonglong2 qa = *(const ulonglong2*)&xs2[p][c];
                ulonglong2 qb = *(const ulonglong2*)&xs2[p][c + 2];
                FFMA2(acc[p], qa.x, p0);
                FFMA2(acc[p], qa.y, p1);
                FFMA2(acc[p], qb.x, p2);
                FFMA2(acc[p], qb.y, p3);
            }
        }
        #pragma unroll
        for (int p = 0; p < NPAIR; p++) {
            float2 f = unpack2(acc[p]);
            h1p[p][tid] = make_float2(fmaxf(f.x, 0.0f), fmaxf(f.y, 0.0f));
        }
    }
    __syncthreads();

    // stage w3 (16KB) into the now-free xs2 space; overlaps with layer2 loads
    float* w3s = (float*)xs2;
    {
        const float4* src = (const float4*)w3;
        float4* dst = (float4*)w3s;
        for (int i = tid; i < 1024; i += 256) dst[i] = src[i];
    }

    // layer 2: h2 = relu(h1 @ w2 + b2); two half-blocks, 4 pairs each.
    {
        int j  = tid & 127;
        int pb = (tid >> 7) * 4;  // pairs pb..pb+3
        ull acc[4];
        {
            float bias = b2[j];
            ull bp = pack2(bias, bias);
            #pragma unroll
            for (int q = 0; q < 4; q++) acc[q] = bp;
        }
        #pragma unroll 2
        for (int c = 0; c < 256; c += 4) {
            float v0 = w2[(c + 0) * 128 + j];
            float v1 = w2[(c + 1) * 128 + j];
            float v2 = w2[(c + 2) * 128 + j];
            float v3 = w2[(c + 3) * 128 + j];
            ull p0 = pack2(v0, v0), p1 = pack2(v1, v1);
            ull p2 = pack2(v2, v2), p3 = pack2(v3, v3);
            #pragma unroll
            for (int q = 0; q < 4; q++) {
                int p = pb + q;
                ulonglong2 qa = *(const ulonglong2*)&h1p[p][c];
                ulonglong2 qb = *(const ulonglong2*)&h1p[p][c + 2];
                FFMA2(acc[q], qa.x, p0);
                FFMA2(acc[q], qa.y, p1);
                FFMA2(acc[q], qb.x, p2);
                FFMA2(acc[q], qb.y, p3);
            }
        }
        #pragma unroll
        for (int q = 0; q < 4; q++) {
            float2 f = unpack2(acc[q]);
            h2p[pb + q][j] = make_float2(fmaxf(f.x, 0.0f), fmaxf(f.y, 0.0f));
        }
    }
    __syncthreads();

    // layer 3 (projection): a = h2 @ w3. Warp w owns center pair w, lane k
    // owns output dim k. Epilogue folds b3 for frame-2 (a2p = b3 - a2).
    {
        int w = tid >> 5;
        int k = tid & 31;
        ull acc0 = 0, acc1 = 0;
        #pragma unroll 4
        for (int d = 0; d < 128; d += 2) {
            ull hv0 = *(const ull*)&h2p[w][d];
            ull hv1 = *(const ull*)&h2p[w][d + 1];
            float s0 = w3s[d * 32 + k];
            float s1 = w3s[(d + 1) * 32 + k];
            ull pw0 = pack2(s0, s0);
            ull pw1 = pack2(s1, s1);
            FFMA2(acc0, hv0, pw0);
            FFMA2(acc1, hv1, pw1);
        }
        float2 fa = unpack2(acc0), fb = unpack2(acc1);
        float r0 = fa.x + fb.x;   // center g0 + 2w
        float r1 = fa.y + fb.y;   // center g0 + 2w + 1
        int gg = g0 + 2 * w;
        if (!frame2) {
            g_a1[gg * 32 + k]       = r0;
            g_a1[(gg + 1) * 32 + k] = r1;
        } else {
            float bk = b3[k];
            g_a2p[(gg - NPTS) * 32 + k]     = bk - r0;
            g_a2p[(gg - NPTS + 1) * 32 + k] = bk - r1;
        }
    }
}

// ---------------------------------------------------------------------------
// Kernel 2: out[m,n] = b4 + sum_k relu(a1[m,k] + a2p[n,k]) * w4[k]
// 256 threads (each owns one n), m-tile 16, grid (4, 64) = 256 CTAs.
// Packed f32x2 add/fma, scalar fmax (alu pipe) on the halves.
// ---------------------------------------------------------------------------
__global__ __launch_bounds__(256) void pair_kernel(
    const float* __restrict__ w4,
    const float* __restrict__ b4,
    float*       __restrict__ out)
{
    __shared__ float a1s[16 * 32];   // 2KB

    const int tid = threadIdx.x;
    const int n   = blockIdx.x * 256 + tid;
    const int m0  = blockIdx.y * 16;

    // stage a1 tile (16 x 32 = 512 floats) via float4
    if (tid < 128)
        ((float4*)a1s)[tid] = ((const float4*)(g_a1 + m0 * 32))[tid];

    // a2p row + w4, packed as 16 f32x2 pairs each
    ull a2p[16], w4p[16];
    {
        const float4* ar = (const float4*)(g_a2p + (long)n * 32);
        const float4* wr = (const float4*)w4;
        #pragma unroll
        for (int v = 0; v < 8; v++) {
            float4 a = ar[v];
            float4 w = wr[v];   // uniform across threads
            a2p[2 * v]     = pack2(a.x, a.y);
            a2p[2 * v + 1] = pack2(a.z, a.w);
            w4p[2 * v]     = pack2(w.x, w.y);
            w4p[2 * v + 1] = pack2(w.z, w.w);
        }
    }
    const float bias = b4[0];
    __syncthreads();

    #pragma unroll 2
    for (int m = 0; m < 16; m++) {
        ull acc0 = 0, acc1 = 0;
        #pragma unroll
        for (int v = 0; v < 16; v += 2) {
            ull av0 = *(const ull*)&a1s[m * 32 + 2 * v];
            ull av1 = *(const ull*)&a1s[m * 32 + 2 * v + 2];
            ull s0, s1;
            FADD2(s0, av0, a2p[v]);
            FADD2(s1, av1, a2p[v + 1]);
            float2 f0 = unpack2(s0), f1 = unpack2(s1);
            s0 = pack2(fmaxf(f0.x, 0.0f), fmaxf(f0.y, 0.0f));
            s1 = pack2(fmaxf(f1.x, 0.0f), fmaxf(f1.y, 0.0f));
            FFMA2(acc0, s0, w4p[v]);
            FFMA2(acc1, s1, w4p[v + 1]);
        }
        float2 r0 = unpack2(acc0), r1 = unpack2(acc1);
        out[(long)(m0 + m) * 1024 + n] = bias + r0.x + r0.y + r1.x + r1.y;
    }
}

// ---------------------------------------------------------------------------
extern "C" void kernel_launch(void* const* d_in, const int* in_sizes, int n_in,
                              void* d_out, int out_size)
{
    const float* feature = (const float*)d_in[0];
    const int*   idx1    = (const int*)  d_in[1];
    const int*   idx2    = (const int*)  d_in[2];
    const float* w1      = (const float*)d_in[3];
    const float* b1      = (const float*)d_in[4];
    const float* w2      = (const float*)d_in[5];
    const float* b2      = (const float*)d_in[6];
    const float* w3      = (const float*)d_in[7];
    const float* b3      = (const float*)d_in[8];
    const float* w4      = (const float*)d_in[9];
    const float* b4      = (const float*)d_in[10];
    float* out = (float*)d_out;

    project_kernel<<<(2 * NPTS) / CPB, 256>>>(feature, idx1, idx2,
                                              w1, b1, w2, b2, w3, b3);
    dim3 grid2(NPTS / 256, NPTS / 16);
    pair_kernel<<<grid2, 256>>>(w4, b4, out);
}

// round 5
// speedup vs baseline: 1.0964x; 1.0964x over previous
#include <cuda_runtime.h>
#include <cuda_bf16.h>

#define CCH   256
#define HH    360
#define WW    360
#define NPTS  1024
#define CPB   16
#define NPAIR (CPB / 2)   // 8 center pairs per block

typedef unsigned long long ull;

// Scratch: a1[m][k] = f1 @ w3 ; a2p[n][k] = b3[k] - (f2 @ w3)[n][k]
__device__ float g_a1[NPTS * 32];
__device__ float g_a2p[NPTS * 32];

#define FFMA2(acc, x, w) \
    asm("fma.rn.f32x2 %0, %1, %2, %0;" : "+l"(acc) : "l"(x), "l"(w))
#define FADD2(d, a, b) \
    asm("add.rn.f32x2 %0, %1, %2;" : "=l"(d) : "l"(a), "l"(b))

__device__ __forceinline__ ull pack2(float a, float b) {
    ull r;
    asm("mov.b64 %0, {%1, %2};" : "=l"(r) : "f"(a), "f"(b));
    return r;
}
__device__ __forceinline__ float2 unpack2(ull v) {
    float2 f;
    asm("mov.b64 {%0, %1}, %2;" : "=f"(f.x), "=f"(f.y) : "l"(v));
    return f;
}

// ---------------------------------------------------------------------------
// Kernel 1: gather + 256->256->128 MLP (relu) + @w3 projection (b3 folded).
// 16 centers per block (8 f32x2 pairs), 512 threads, 128 blocks.
// Layers 1-2 use split-K partial sums so all 16 warps work with zero
// duplicated weight traffic.
// Shared memory (48KB, overlaid):
//   smemA: xs2[8][256] (gathered feats)      -> w3s[128*32] after layer1
//   smemB: part1[8][256]                     -> part2[8][128] | h2p[8][128]
//   smemC: h1p[8][256]
// ---------------------------------------------------------------------------
__global__ __launch_bounds__(512) void project_kernel(
    const float* __restrict__ feature,
    const int*   __restrict__ idx1,
    const int*   __restrict__ idx2,
    const float* __restrict__ w1, const float* __restrict__ b1,
    const float* __restrict__ w2, const float* __restrict__ b2,
    const float* __restrict__ w3, const float* __restrict__ b3)
{
    __shared__ float2 smemA[NPAIR * 256];   // 16KB
    __shared__ float2 smemB[NPAIR * 256];   // 16KB
    __shared__ float2 smemC[NPAIR * 256];   // 16KB

    float2 (*xs2)[256] = (float2 (*)[256])smemA;
    float*  w3s        = (float*)smemA;
    float2 (*part1)[256] = (float2 (*)[256])smemB;
    float2* part2      = smemB;              // [8][128] float2 = 8KB
    float2 (*h2p)[128] = (float2 (*)[128])(smemB + 1024); // 8KB
    float2 (*h1p)[256] = (float2 (*)[256])smemC;

    const int tid = threadIdx.x;
    const int g0  = blockIdx.x * CPB;
    const bool frame2 = (g0 >= NPTS);
    const int* __restrict__ idx = frame2 ? idx2 : idx1;
    const int  i0 = frame2 ? (g0 - NPTS) : g0;

    // ---- gather: 16 centers x 256 channels = 4096 loads over 512 threads
    #pragma unroll
    for (int i = 0; i < 8; i++) {
        int e  = tid + i * 512;
        int t  = e >> 8;
        int ch = e & 255;
        int b  = __ldg(&idx[i0 + t]);
        int hh = __ldg(&idx[NPTS + i0 + t]);
        int ww = __ldg(&idx[2 * NPTS + i0 + t]);
        long off = (((long)b * CCH + ch) * HH + hh) * (long)WW + ww;
        ((float*)&xs2[t >> 1][ch])[t & 1] = __ldg(&feature[off]);
    }
    __syncthreads();

    // ---- layer 1: h1 = relu(x @ w1 + b1)
    // thread (j = tid&255, h = tid>>8): output col j, channel half h.
    {
        const int j = tid & 255;
        const int h = tid >> 8;
        const int cbase = h * 128;
        ull acc[NPAIR];
        {
            ull init;
            if (h) init = 0ULL;
            else { float bb = b1[j]; init = pack2(bb, bb); }
            #pragma unroll
            for (int p = 0; p < NPAIR; p++) acc[p] = init;
        }
        #pragma unroll 2
        for (int c0 = 0; c0 < 128; c0 += 4) {
            int c = cbase + c0;
            float v0 = w1[(c + 0) * 256 + j];
            float v1 = w1[(c + 1) * 256 + j];
            float v2 = w1[(c + 2) * 256 + j];
            float v3 = w1[(c + 3) * 256 + j];
            ull p0 = pack2(v0, v0), p1 = pack2(v1, v1);
            ull p2 = pack2(v2, v2), p3 = pack2(v3, v3);
            #pragma unroll
            for (int p = 0; p < NPAIR; p++) {
                ulonglong2 qa = *(const ulonglong2*)&xs2[p][c];
                ulonglong2 qb = *(const ulonglong2*)&xs2[p][c + 2];
                FFMA2(acc[p], qa.x, p0);
                FFMA2(acc[p], qa.y, p1);
                FFMA2(acc[p], qb.x, p2);
                FFMA2(acc[p], qb.y, p3);
            }
        }
        if (h) {
            #pragma unroll
            for (int p = 0; p < NPAIR; p++)
                part1[p][j] = unpack2(acc[p]);
        }
        __syncthreads();   // xs2 dead; part1 ready
        if (!h) {
            #pragma unroll
            for (int p = 0; p < NPAIR; p++) {
                float2 f = unpack2(acc[p]);
                float2 g = part1[p][j];
                h1p[p][j] = make_float2(fmaxf(f.x + g.x, 0.0f),
                                        fmaxf(f.y + g.y, 0.0f));
            }
        } else {
            // h==1 threads stage w3 into the freed xs2 region
            const float4* src = (const float4*)w3;
            float4* dst = (float4*)w3s;
            int l = tid - 256;
            #pragma unroll
            for (int i = 0; i < 4; i++) dst[l + i * 256] = src[l + i * 256];
        }
    }
    __syncthreads();

    // ---- layer 2: h2 = relu(h1 @ w2 + b2)
    // thread (j2 = tid&127, q = tid>>7): qc = channel half, qp = pair half.
    {
        const int j2 = tid & 127;
        const int q  = tid >> 7;
        const int qc = q & 1;
        const int qp = q >> 1;
        const int cbase = qc * 128;
        const int pb = qp * 4;
        ull acc[4];
        {
            ull init;
            if (qc) init = 0ULL;
            else { float bb = b2[j2]; init = pack2(bb, bb); }
            #pragma unroll
            for (int u = 0; u < 4; u++) acc[u] = init;
        }
        #pragma unroll 2
        for (int c0 = 0; c0 < 128; c0 += 4) {
            int c = cbase + c0;
            float v0 = w2[(c + 0) * 128 + j2];
            float v1 = w2[(c + 1) * 128 + j2];
            float v2 = w2[(c + 2) * 128 + j2];
            float v3 = w2[(c + 3) * 128 + j2];
            ull p0 = pack2(v0, v0), p1 = pack2(v1, v1);
            ull p2 = pack2(v2, v2), p3 = pack2(v3, v3);
            #pragma unroll
            for (int u = 0; u < 4; u++) {
                int p = pb + u;
                ulonglong2 qa = *(const ulonglong2*)&h1p[p][c];
                ulonglong2 qb = *(const ulonglong2*)&h1p[p][c + 2];
                FFMA2(acc[u], qa.x, p0);
                FFMA2(acc[u], qa.y, p1);
                FFMA2(acc[u], qb.x, p2);
                FFMA2(acc[u], qb.y, p3);
            }
        }
        if (qc) {
            #pragma unroll
            for (int u = 0; u < 4; u++)
                part2[(qp * 4 + u) * 128 + j2] = unpack2(acc[u]);
        }
        __syncthreads();   // part1 dead; part2 ready
        if (!qc) {
            #pragma unroll
            for (int u = 0; u < 4; u++) {
                float2 f = unpack2(acc[u]);
                float2 g = part2[(qp * 4 + u) * 128 + j2];
                h2p[pb + u][j2] = make_float2(fmaxf(f.x + g.x, 0.0f),
                                              fmaxf(f.y + g.y, 0.0f));
            }
        }
    }
    __syncthreads();

    // ---- layer 3 (projection): a = h2 @ w3, b3 folded for frame 2.
    // 16 warps, warp w -> center w; lane k -> output dim k.
    {
        const int w = tid >> 5;       // 0..15 = center
        const int k = tid & 31;
        const int p = w >> 1;
        const int hl = w & 1;
        float acc0 = 0.0f, acc1 = 0.0f, acc2 = 0.0f, acc3 = 0.0f;
        #pragma unroll 8
        for (int d = 0; d < 128; d += 4) {
            float hv0 = ((const float*)&h2p[p][d + 0])[hl];
            float hv1 = ((const float*)&h2p[p][d + 1])[hl];
            float hv2 = ((const float*)&h2p[p][d + 2])[hl];
            float hv3 = ((const float*)&h2p[p][d + 3])[hl];
            acc0 = fmaf(hv0, w3s[(d + 0) * 32 + k], acc0);
            acc1 = fmaf(hv1, w3s[(d + 1) * 32 + k], acc1);
            acc2 = fmaf(hv2, w3s[(d + 2) * 32 + k], acc2);
            acc3 = fmaf(hv3, w3s[(d + 3) * 32 + k], acc3);
        }
        float r = (acc0 + acc1) + (acc2 + acc3);
        int gg = g0 + w;
        if (!frame2) {
            g_a1[gg * 32 + k] = r;
        } else {
            g_a2p[(gg - NPTS) * 32 + k] = b3[k] - r;
        }
    }
}

// ---------------------------------------------------------------------------
// Kernel 2: out[m,n] = b4 + sum_k relu(a1[m,k] + a2p[n,k]) * w4[k]
// 256 threads (each owns one n), m-tile 8, grid (4, 128) = 512 CTAs.
// FIXED: k-loop now covers all 8 ulonglong2 chunks (32 dims), not 4.
// ---------------------------------------------------------------------------
__global__ __launch_bounds__(256) void pair_kernel(
    const float* __restrict__ w4,
    const float* __restrict__ b4,
    float*       __restrict__ out)
{
    __shared__ float a1s[8 * 32];   // 1KB

    const int tid = threadIdx.x;
    const int n   = blockIdx.x * 256 + tid;
    const int m0  = blockIdx.y * 8;

    // stage a1 tile (8 x 32 = 256 floats) via float4
    if (tid < 64)
        ((float4*)a1s)[tid] = ((const float4*)(g_a1 + m0 * 32))[tid];

    // a2p row + w4, packed as 16 f32x2 pairs each
    ull a2p[16], w4p[16];
    {
        const float4* ar = (const float4*)(g_a2p + (long)n * 32);
        const float4* wr = (const float4*)w4;
        #pragma unroll
        for (int v = 0; v < 8; v++) {
            float4 a = ar[v];
            float4 w = wr[v];
            a2p[2 * v]     = pack2(a.x, a.y);
            a2p[2 * v + 1] = pack2(a.z, a.w);
            w4p[2 * v]     = pack2(w.x, w.y);
            w4p[2 * v + 1] = pack2(w.z, w.w);
        }
    }
    const float bias = b4[0];
    __syncthreads();

    #pragma unroll
    for (int m = 0; m < 8; m++) {
        const ulonglong2* ap = (const ulonglong2*)&a1s[m * 32];
        ull acc0 = pack2(bias, 0.0f), acc1 = 0ULL;
        #pragma unroll
        for (int v = 0; v < 8; v++) {      // 8 chunks x 4 dims = all 32 dims
            ulonglong2 qa = ap[v];         // a1 dims 4v .. 4v+3
            ull s0, s1;
            FADD2(s0, qa.x, a2p[2 * v + 0]);
            FADD2(s1, qa.y, a2p[2 * v + 1]);
            float2 f0 = unpack2(s0), f1 = unpack2(s1);
            s0 = pack2(fmaxf(f0.x, 0.0f), fmaxf(f0.y, 0.0f));
            s1 = pack2(fmaxf(f1.x, 0.0f), fmaxf(f1.y, 0.0f));
            FFMA2(acc0, s0, w4p[2 * v + 0]);
            FFMA2(acc1, s1, w4p[2 * v + 1]);
        }
        float2 r0 = unpack2(acc0), r1 = unpack2(acc1);
        out[(long)(m0 + m) * 1024 + n] = (r0.x + r0.y) + (r1.x + r1.y);
    }
}

// ---------------------------------------------------------------------------
extern "C" void kernel_launch(void* const* d_in, const int* in_sizes, int n_in,
                              void* d_out, int out_size)
{
    const float* feature = (const float*)d_in[0];
    const int*   idx1    = (const int*)  d_in[1];
    const int*   idx2    = (const int*)  d_in[2];
    const float* w1      = (const float*)d_in[3];
    const float* b1      = (const float*)d_in[4];
    const float* w2      = (const float*)d_in[5];
    const float* b2      = (const float*)d_in[6];
    const float* w3      = (const float*)d_in[7];
    const float* b3      = (const float*)d_in[8];
    const float* w4      = (const float*)d_in[9];
    const float* b4      = (const float*)d_in[10];
    float* out = (float*)d_out;

    project_kernel<<<(2 * NPTS) / CPB, 512>>>(feature, idx1, idx2,
                                              w1, b1, w2, b2, w3, b3);
    dim3 grid2(NPTS / 256, NPTS / 8);
    pair_kernel<<<grid2, 256>>>(w4, b4, out);
}

// round 6
// speedup vs baseline: 1.1020x; 1.0051x over previous
#include <cuda_runtime.h>
#include <cuda_bf16.h>

#define CCH   256
#define HH    360
#define WW    360
#define NPTS  1024
#define CPB   16
#define NPAIR (CPB / 2)   // 8 center pairs per block

typedef unsigned long long ull;

// Scratch: a1[m][k] = f1 @ w3 ; a2p[n][k] = b3[k] - (f2 @ w3)[n][k]
__device__ float g_a1[NPTS * 32];
__device__ float g_a2p[NPTS * 32];

#define FFMA2(acc, x, w) \
    asm("fma.rn.f32x2 %0, %1, %2, %0;" : "+l"(acc) : "l"(x), "l"(w))
#define FADD2(d, a, b) \
    asm("add.rn.f32x2 %0, %1, %2;" : "=l"(d) : "l"(a), "l"(b))

__device__ __forceinline__ ull pack2(float a, float b) {
    ull r;
    asm("mov.b64 %0, {%1, %2};" : "=l"(r) : "f"(a), "f"(b));
    return r;
}
__device__ __forceinline__ float2 unpack2(ull v) {
    float2 f;
    asm("mov.b64 {%0, %1}, %2;" : "=f"(f.x), "=f"(f.y) : "l"(v));
    return f;
}

// ---------------------------------------------------------------------------
// Kernel 1: gather + 256->256->128 MLP (relu) + @w3 projection (b3 folded).
// 16 centers per block, 512 threads, 128 blocks, split-K partial sums,
// software-pipelined weight prefetch in layers 1-2.
// Shared memory (48KB, overlaid):
//   smemA: xs2[8][256]  -> w3s[128*32] after layer1
//   smemB: part1[8][256] -> part2[8][128] | h2p[8][128]
//   smemC: h1p[8][256]
// ---------------------------------------------------------------------------
__global__ __launch_bounds__(512) void project_kernel(
    const float* __restrict__ feature,
    const int*   __restrict__ idx1,
    const int*   __restrict__ idx2,
    const float* __restrict__ w1, const float* __restrict__ b1,
    const float* __restrict__ w2, const float* __restrict__ b2,
    const float* __restrict__ w3, const float* __restrict__ b3)
{
    __shared__ float2 smemA[NPAIR * 256];   // 16KB
    __shared__ float2 smemB[NPAIR * 256];   // 16KB
    __shared__ float2 smemC[NPAIR * 256];   // 16KB

    float2 (*xs2)[256] = (float2 (*)[256])smemA;
    float*  w3s        = (float*)smemA;
    float2 (*part1)[256] = (float2 (*)[256])smemB;
    float2* part2      = smemB;              // [8][128] float2 = 8KB
    float2 (*h2p)[128] = (float2 (*)[128])(smemB + 1024); // 8KB
    float2 (*h1p)[256] = (float2 (*)[256])smemC;

    const int tid = threadIdx.x;
    const int g0  = blockIdx.x * CPB;
    const bool frame2 = (g0 >= NPTS);
    const int* __restrict__ idx = frame2 ? idx2 : idx1;
    const int  i0 = frame2 ? (g0 - NPTS) : g0;

    // ---- gather: 16 centers x 256 channels = 4096 loads over 512 threads
    #pragma unroll
    for (int i = 0; i < 8; i++) {
        int e  = tid + i * 512;
        int t  = e >> 8;
        int ch = e & 255;
        int b  = __ldg(&idx[i0 + t]);
        int hh = __ldg(&idx[NPTS + i0 + t]);
        int ww = __ldg(&idx[2 * NPTS + i0 + t]);
        long off = (((long)b * CCH + ch) * HH + hh) * (long)WW + ww;
        ((float*)&xs2[t >> 1][ch])[t & 1] = __ldg(&feature[off]);
    }
    __syncthreads();

    // ---- layer 1: h1 = relu(x @ w1 + b1)
    // thread (j = tid&255, h = tid>>8): output col j, channel half h.
    {
        const int j = tid & 255;
        const int h = tid >> 8;
        const int cbase = h * 128;
        ull acc[NPAIR];
        {
            ull init;
            if (h) init = 0ULL;
            else { float bb = b1[j]; init = pack2(bb, bb); }
            #pragma unroll
            for (int p = 0; p < NPAIR; p++) acc[p] = init;
        }
        // prefetch step 0
        float cv0 = w1[(cbase + 0) * 256 + j];
        float cv1 = w1[(cbase + 1) * 256 + j];
        float cv2 = w1[(cbase + 2) * 256 + j];
        float cv3 = w1[(cbase + 3) * 256 + j];
        #pragma unroll 4
        for (int c0 = 0; c0 < 128; c0 += 4) {
            int cn = cbase + ((c0 + 4) & 127);   // wraps (redundant) on last
            float nv0 = w1[(cn + 0) * 256 + j];
            float nv1 = w1[(cn + 1) * 256 + j];
            float nv2 = w1[(cn + 2) * 256 + j];
            float nv3 = w1[(cn + 3) * 256 + j];
            ull p0 = pack2(cv0, cv0), p1 = pack2(cv1, cv1);
            ull p2 = pack2(cv2, cv2), p3 = pack2(cv3, cv3);
            int c = cbase + c0;
            #pragma unroll
            for (int p = 0; p < NPAIR; p++) {
                ulonglong2 qa = *(const ulonglong2*)&xs2[p][c];
                ulonglong2 qb = *(const ulonglong2*)&xs2[p][c + 2];
                FFMA2(acc[p], qa.x, p0);
                FFMA2(acc[p], qa.y, p1);
                FFMA2(acc[p], qb.x, p2);
                FFMA2(acc[p], qb.y, p3);
            }
            cv0 = nv0; cv1 = nv1; cv2 = nv2; cv3 = nv3;
        }
        if (h) {
            #pragma unroll
            for (int p = 0; p < NPAIR; p++)
                part1[p][j] = unpack2(acc[p]);
        }
        __syncthreads();   // xs2 dead; part1 ready
        if (!h) {
            #pragma unroll
            for (int p = 0; p < NPAIR; p++) {
                float2 f = unpack2(acc[p]);
                float2 g = part1[p][j];
                h1p[p][j] = make_float2(fmaxf(f.x + g.x, 0.0f),
                                        fmaxf(f.y + g.y, 0.0f));
            }
        } else {
            // h==1 threads stage w3 into the freed xs2 region
            const float4* src = (const float4*)w3;
            float4* dst = (float4*)w3s;
            int l = tid - 256;
            #pragma unroll
            for (int i = 0; i < 4; i++) dst[l + i * 256] = src[l + i * 256];
        }
    }
    __syncthreads();

    // ---- layer 2: h2 = relu(h1 @ w2 + b2)
    // thread (j2 = tid&127, q = tid>>7): qc = channel half, qp = pair half.
    {
        const int j2 = tid & 127;
        const int q  = tid >> 7;
        const int qc = q & 1;
        const int qp = q >> 1;
        const int cbase = qc * 128;
        const int pb = qp * 4;
        ull acc[4];
        {
            ull init;
            if (qc) init = 0ULL;
            else { float bb = b2[j2]; init = pack2(bb, bb); }
            #pragma unroll
            for (int u = 0; u < 4; u++) acc[u] = init;
        }
        float cv0 = w2[(cbase + 0) * 128 + j2];
        float cv1 = w2[(cbase + 1) * 128 + j2];
        float cv2 = w2[(cbase + 2) * 128 + j2];
        float cv3 = w2[(cbase + 3) * 128 + j2];
        #pragma unroll 4
        for (int c0 = 0; c0 < 128; c0 += 4) {
            int cn = cbase + ((c0 + 4) & 127);
            float nv0 = w2[(cn + 0) * 128 + j2];
            float nv1 = w2[(cn + 1) * 128 + j2];
            float nv2 = w2[(cn + 2) * 128 + j2];
            float nv3 = w2[(cn + 3) * 128 + j2];
            ull p0 = pack2(cv0, cv0), p1 = pack2(cv1, cv1);
            ull p2 = pack2(cv2, cv2), p3 = pack2(cv3, cv3);
            int c = cbase + c0;
            #pragma unroll
            for (int u = 0; u < 4; u++) {
                int p = pb + u;
                ulonglong2 qa = *(const ulonglong2*)&h1p[p][c];
                ulonglong2 qb = *(const ulonglong2*)&h1p[p][c + 2];
                FFMA2(acc[u], qa.x, p0);
                FFMA2(acc[u], qa.y, p1);
                FFMA2(acc[u], qb.x, p2);
                FFMA2(acc[u], qb.y, p3);
            }
            cv0 = nv0; cv1 = nv1; cv2 = nv2; cv3 = nv3;
        }
        if (qc) {
            #pragma unroll
            for (int u = 0; u < 4; u++)
                part2[(qp * 4 + u) * 128 + j2] = unpack2(acc[u]);
        }
        __syncthreads();   // part1 dead; part2 ready
        if (!qc) {
            #pragma unroll
            for (int u = 0; u < 4; u++) {
                float2 f = unpack2(acc[u]);
                float2 g = part2[(qp * 4 + u) * 128 + j2];
                h2p[pb + u][j2] = make_float2(fmaxf(f.x + g.x, 0.0f),
                                              fmaxf(f.y + g.y, 0.0f));
            }
        }
    }
    __syncthreads();

    // ---- layer 3 (projection): a = h2 @ w3, b3 folded for frame 2.
    // 16 warps, warp w -> center w; lane k -> output dim k.
    {
        const int w = tid >> 5;       // 0..15 = center
        const int k = tid & 31;
        const int p = w >> 1;
        const int hl = w & 1;
        float acc0 = 0.0f, acc1 = 0.0f, acc2 = 0.0f, acc3 = 0.0f;
        #pragma unroll 8
        for (int d = 0; d < 128; d += 4) {
            float hv0 = ((const float*)&h2p[p][d + 0])[hl];
            float hv1 = ((const float*)&h2p[p][d + 1])[hl];
            float hv2 = ((const float*)&h2p[p][d + 2])[hl];
            float hv3 = ((const float*)&h2p[p][d + 3])[hl];
            acc0 = fmaf(hv0, w3s[(d + 0) * 32 + k], acc0);
            acc1 = fmaf(hv1, w3s[(d + 1) * 32 + k], acc1);
            acc2 = fmaf(hv2, w3s[(d + 2) * 32 + k], acc2);
            acc3 = fmaf(hv3, w3s[(d + 3) * 32 + k], acc3);
        }
        float r = (acc0 + acc1) + (acc2 + acc3);
        int gg = g0 + w;
        if (!frame2) {
            g_a1[gg * 32 + k] = r;
        } else {
            g_a2p[(gg - NPTS) * 32 + k] = b3[k] - r;
        }
    }
}

// ---------------------------------------------------------------------------
// Kernel 2: out[m,n] = b4 + sum_k relu(a1[m,k] + a2p[n,k]) * w4[k]
// 512 threads (each owns one n), m-tile 16, grid (2, 64) = 128 CTAs
// (single wave, 16 warps/SM, prologue amortized over 16 m-rows).
// ---------------------------------------------------------------------------
__global__ __launch_bounds__(512) void pair_kernel(
    const float* __restrict__ w4,
    const float* __restrict__ b4,
    float*       __restrict__ out)
{
    __shared__ float a1s[16 * 32];   // 2KB

    const int tid = threadIdx.x;
    const int n   = blockIdx.x * 512 + tid;
    const int m0  = blockIdx.y * 16;

    // stage a1 tile (16 x 32 = 512 floats) via float4
    if (tid < 128)
        ((float4*)a1s)[tid] = ((const float4*)(g_a1 + m0 * 32))[tid];

    // a2p row + w4, packed as 16 f32x2 pairs each
    ull a2p[16], w4p[16];
    {
        const float4* ar = (const float4*)(g_a2p + (long)n * 32);
        const float4* wr = (const float4*)w4;
        #pragma unroll
        for (int v = 0; v < 8; v++) {
            float4 a = ar[v];
            float4 w = wr[v];
            a2p[2 * v]     = pack2(a.x, a.y);
            a2p[2 * v + 1] = pack2(a.z, a.w);
            w4p[2 * v]     = pack2(w.x, w.y);
            w4p[2 * v + 1] = pack2(w.z, w.w);
        }
    }
    const float bias = b4[0];
    __syncthreads();

    #pragma unroll 4
    for (int m = 0; m < 16; m++) {
        const ulonglong2* ap = (const ulonglong2*)&a1s[m * 32];
        ull acc0 = pack2(bias, 0.0f), acc1 = 0ULL;
        #pragma unroll
        for (int v = 0; v < 8; v++) {      // 8 chunks x 4 dims = 32 dims
            ulonglong2 qa = ap[v];         // a1 dims 4v .. 4v+3
            ull s0, s1;
            FADD2(s0, qa.x, a2p[2 * v + 0]);
            FADD2(s1, qa.y, a2p[2 * v + 1]);
            float2 f0 = unpack2(s0), f1 = unpack2(s1);
            s0 = pack2(fmaxf(f0.x, 0.0f), fmaxf(f0.y, 0.0f));
            s1 = pack2(fmaxf(f1.x, 0.0f), fmaxf(f1.y, 0.0f));
            FFMA2(acc0, s0, w4p[2 * v + 0]);
            FFMA2(acc1, s1, w4p[2 * v + 1]);
        }
        float2 r0 = unpack2(acc0), r1 = unpack2(acc1);
        out[(long)(m0 + m) * 1024 + n] = (r0.x + r0.y) + (r1.x + r1.y);
    }
}

// ---------------------------------------------------------------------------
extern "C" void kernel_launch(void* const* d_in, const int* in_sizes, int n_in,
                              void* d_out, int out_size)
{
    const float* feature = (const float*)d_in[0];
    const int*   idx1    = (const int*)  d_in[1];
    const int*   idx2    = (const int*)  d_in[2];
    const float* w1      = (const float*)d_in[3];
    const float* b1      = (const float*)d_in[4];
    const float* w2      = (const float*)d_in[5];
    const float* b2      = (const float*)d_in[6];
    const float* w3      = (const float*)d_in[7];
    const float* b3      = (const float*)d_in[8];
    const float* w4      = (const float*)d_in[9];
    const float* b4      = (const float*)d_in[10];
    float* out = (float*)d_out;

    project_kernel<<<(2 * NPTS) / CPB, 512>>>(feature, idx1, idx2,
                                              w1, b1, w2, b2, w3, b3);
    dim3 grid2(NPTS / 512, NPTS / 16);
    pair_kernel<<<grid2, 512>>>(w4, b4, out);
}